// round 8
// baseline (speedup 1.0000x reference)
#include <cuda_runtime.h>

static constexpr int B_  = 16;
static constexpr int H_  = 2048;
static constexpr int I_  = 1024;
static constexpr int NT  = 256;   // 8 warps; each thread owns 8 columns (2 float4 groups)

__device__ __forceinline__ float flg2(float x){ float r; asm("lg2.approx.f32 %0,%1;" : "=f"(r) : "f"(x)); return r; }
__device__ __forceinline__ float frcp(float x){ float r; asm("rcp.approx.f32 %0,%1;" : "=f"(r) : "f"(x)); return r; }
__device__ __forceinline__ float fex2(float x){ float r; asm("ex2.approx.f32 %0,%1;" : "=f"(r) : "f"(x)); return r; }

// w = se / (-ln u) = (-se*log2e) * rcp(lg2(u)).
// Clamp lg2(u) <= -4e-8 (|lg2| of the largest float < 1): protects against
// lg2.approx's 2^-22 abs error flipping the sign near u=1; the clamped weight
// is huge -> dominates num AND den -> output -> h of that element, which is
// the true u->1 limit, so the approximation error cancels.
// u = 0 -> lg2 = -inf -> rcp = -0 -> w = +0 (reference weight there ~0.04*se,
// negligible among a ~2e4*se row sum).
__device__ __forceinline__ float gwr(float u) {
    return frcp(fminf(flg2(u), -4e-8f));   // negative result; nse sign restores +
}

__global__ __launch_bounds__(NT, 5) void reservoir_cell_kernel(
    const float* __restrict__ x_t,         // (B, I)
    const float* __restrict__ h_prev,      // (B, H)
    const float* __restrict__ W_ih_w,      // (H, I)
    const float* __restrict__ W_ih_b,      // (H,)
    const float* __restrict__ W_hh,        // (H, H)
    const float* __restrict__ hh_mask,     // (H, H)
    const float* __restrict__ temperature, // (1,)
    const float* __restrict__ gumbel,      // (B, H, H) uniform(0,1)
    float* __restrict__ out)               // (B, H)
{
    __shared__ float  s_red[8];
    __shared__ float  s_ic[B_];
    __shared__ float2 s_part[B_][NT];      // 32 KB: per-thread (num,den) partials

    const int o   = blockIdx.x;
    const int tid = threadIdx.x;
    const int wid = tid >> 5;
    const int lid = tid & 31;

    // logits scale folded with log2(e): phase 1 works directly in log2 domain
    const float s_l2 = 1.4426950408889634f / fmaxf(temperature[0], 1e-3f);

    // ---------- phase 1: row logits (log2 domain), block max, nse[8] in regs ----------
    const float4* wrow = reinterpret_cast<const float4*>(W_hh    + (size_t)o * H_);
    const float4* mrow = reinterpret_cast<const float4*>(hh_mask + (size_t)o * H_);
    float4 wa = wrow[tid], wb = wrow[tid + NT];
    float4 ma = mrow[tid], mb = mrow[tid + NT];
    float e[8];
    e[0] = wa.x*ma.x*s_l2; e[1] = wa.y*ma.y*s_l2; e[2] = wa.z*ma.z*s_l2; e[3] = wa.w*ma.w*s_l2;
    e[4] = wb.x*mb.x*s_l2; e[5] = wb.y*mb.y*s_l2; e[6] = wb.z*mb.z*s_l2; e[7] = wb.w*mb.w*s_l2;

    float m = e[0];
    #pragma unroll
    for (int j = 1; j < 8; j++) m = fmaxf(m, e[j]);
    #pragma unroll
    for (int s = 16; s; s >>= 1) m = fmaxf(m, __shfl_xor_sync(0xffffffffu, m, s));
    if (lid == 0) s_red[wid] = m;
    __syncthreads();
    m = s_red[0];
    #pragma unroll
    for (int j = 1; j < 8; j++) m = fmaxf(m, s_red[j]);

    // nse = -se * log2(e): sign + 1/ln2 folded so hot loop does w = nse * rcp(lg2 u)
    float nse[8];
    #pragma unroll
    for (int j = 0; j < 8; j++) nse[j] = -1.4426950408889634f * fex2(e[j] - m);

    // ---------- phase 3: stream gumbel (evict-first); ptxas-scheduled loads ----------
    const size_t bstride4 = (size_t)H_ * H_ / 4;           // float4 stride between batches
    const float4* gu = reinterpret_cast<const float4*>(gumbel + (size_t)o * H_) + tid;
    const float4* hp = reinterpret_cast<const float4*>(h_prev) + tid;

    #pragma unroll 4
    for (int b = 0; b < B_; b++) {
        const float4 ua = __ldcs(gu + (size_t)b * bstride4);
        const float4 ub = __ldcs(gu + (size_t)b * bstride4 + NT);
        const float4 ha = __ldg(hp + (size_t)b * (H_ / 4));
        const float4 hb = __ldg(hp + (size_t)b * (H_ / 4) + NT);

        float n0 = 0.f, d0 = 0.f, n1 = 0.f, d1 = 0.f;   // dual accumulators
        float w;
        w = nse[0] * gwr(ua.x); n0 = fmaf(w, ha.x, n0); d0 += w;
        w = nse[1] * gwr(ua.y); n1 = fmaf(w, ha.y, n1); d1 += w;
        w = nse[2] * gwr(ua.z); n0 = fmaf(w, ha.z, n0); d0 += w;
        w = nse[3] * gwr(ua.w); n1 = fmaf(w, ha.w, n1); d1 += w;
        w = nse[4] * gwr(ub.x); n0 = fmaf(w, hb.x, n0); d0 += w;
        w = nse[5] * gwr(ub.y); n1 = fmaf(w, hb.y, n1); d1 += w;
        w = nse[6] * gwr(ub.z); n0 = fmaf(w, hb.z, n0); d0 += w;
        w = nse[7] * gwr(ub.w); n1 = fmaf(w, hb.w, n1); d1 += w;

        s_part[b][tid] = make_float2(n0 + n1, d0 + d1);  // contiguous 256B/warp
    }

    // ---------- phase 2: input contribution; warp w -> batches w and w+8 ----------
    // (after the gumbel stream so the DRAM-critical loop starts ASAP)
    {
        const float4* wr = reinterpret_cast<const float4*>(W_ih_w + (size_t)o * I_);
        const float4* x0 = reinterpret_cast<const float4*>(x_t + (size_t)wid * I_);
        const float4* x1 = reinterpret_cast<const float4*>(x_t + (size_t)(wid + 8) * I_);
        float a0 = 0.f, a1 = 0.f;
        #pragma unroll
        for (int k = lid; k < I_ / 4; k += 32) {
            float4 wv = wr[k];
            float4 v0 = x0[k];
            float4 v1 = x1[k];
            a0 = fmaf(wv.x, v0.x, a0); a0 = fmaf(wv.y, v0.y, a0);
            a0 = fmaf(wv.z, v0.z, a0); a0 = fmaf(wv.w, v0.w, a0);
            a1 = fmaf(wv.x, v1.x, a1); a1 = fmaf(wv.y, v1.y, a1);
            a1 = fmaf(wv.z, v1.z, a1); a1 = fmaf(wv.w, v1.w, a1);
        }
        #pragma unroll
        for (int s = 16; s; s >>= 1) {
            a0 += __shfl_xor_sync(0xffffffffu, a0, s);
            a1 += __shfl_xor_sync(0xffffffffu, a1, s);
        }
        if (lid == 0) {
            float bias = W_ih_b[o];
            s_ic[wid]     = a0 + bias;
            s_ic[wid + 8] = a1 + bias;
        }
    }
    __syncthreads();

    // ---------- phase 4: one-time reduction; warp w -> batches 2w, 2w+1 ----------
    #pragma unroll
    for (int k = 0; k < 2; k++) {
        const int b = 2 * wid + k;
        const float4* row = reinterpret_cast<const float4*>(&s_part[b][0]);   // 128 float4
        float4 p0 = row[lid], p1 = row[lid + 32], p2 = row[lid + 64], p3 = row[lid + 96];
        float ns = (p0.x + p1.x) + (p2.x + p3.x) + (p0.z + p1.z) + (p2.z + p3.z);
        float ds = (p0.y + p1.y) + (p2.y + p3.y) + (p0.w + p1.w) + (p2.w + p3.w);
        #pragma unroll
        for (int s = 16; s; s >>= 1) {
            ns += __shfl_xor_sync(0xffffffffu, ns, s);
            ds += __shfl_xor_sync(0xffffffffu, ds, s);
        }
        if (lid == 0) out[(size_t)b * H_ + o] = tanhf(s_ic[b] + ns / ds);
    }
}

extern "C" void kernel_launch(void* const* d_in, const int* in_sizes, int n_in,
                              void* d_out, int out_size) {
    const float* x_t         = (const float*)d_in[0];
    const float* h_prev      = (const float*)d_in[1];
    const float* W_ih_w      = (const float*)d_in[2];
    const float* W_ih_b      = (const float*)d_in[3];
    const float* W_hh        = (const float*)d_in[4];
    const float* hh_mask     = (const float*)d_in[5];
    const float* temperature = (const float*)d_in[6];
    const float* gumbel      = (const float*)d_in[7];
    float* out = (float*)d_out;

    reservoir_cell_kernel<<<H_, NT>>>(x_t, h_prev, W_ih_w, W_ih_b, W_hh, hh_mask,
                                      temperature, gumbel, out);
}

// round 9
// speedup vs baseline: 1.0360x; 1.0360x over previous
#include <cuda_runtime.h>

static constexpr int B_  = 16;
static constexpr int H_  = 2048;
static constexpr int I_  = 1024;
static constexpr int NT  = 256;   // 8 warps; each thread owns 8 columns (2 float4 groups)

__device__ __forceinline__ float flg2(float x){ float r; asm("lg2.approx.f32 %0,%1;" : "=f"(r) : "f"(x)); return r; }
__device__ __forceinline__ float frcp(float x){ float r; asm("rcp.approx.f32 %0,%1;" : "=f"(r) : "f"(x)); return r; }
__device__ __forceinline__ float fex2(float x){ float r; asm("ex2.approx.f32 %0,%1;" : "=f"(r) : "f"(x)); return r; }

// w = se / (-ln u) = (-se*log2e) * rcp(lg2(u)).
// Clamp lg2(u) <= -4e-8 (|lg2| of the largest float < 1): protects against
// lg2.approx's 2^-22 abs error flipping the sign near u=1; the clamped weight
// is huge -> dominates num AND den -> output -> h of that element, which is
// the true u->1 limit, so the approximation error cancels.
// u = 0 -> lg2 = -inf -> rcp = -0 -> w = +0 (reference weight there ~0.04*se,
// negligible among a ~2e4*se row sum).
__device__ __forceinline__ float gwr(float u) {
    return frcp(fminf(flg2(u), -4e-8f));   // negative result; nse sign restores +
}

__global__ __launch_bounds__(NT, 5) void reservoir_cell_kernel(
    const float* __restrict__ x_t,         // (B, I)
    const float* __restrict__ h_prev,      // (B, H)
    const float* __restrict__ W_ih_w,      // (H, I)
    const float* __restrict__ W_ih_b,      // (H,)
    const float* __restrict__ W_hh,        // (H, H)
    const float* __restrict__ hh_mask,     // (H, H)
    const float* __restrict__ temperature, // (1,)
    const float* __restrict__ gumbel,      // (B, H, H) uniform(0,1)
    float* __restrict__ out)               // (B, H)
{
    __shared__ float  s_red[8];
    __shared__ float  s_ic[B_];
    __shared__ float2 s_part[B_][NT];      // 32 KB: per-thread (num,den) partials

    const int o   = blockIdx.x;
    const int tid = threadIdx.x;
    const int wid = tid >> 5;
    const int lid = tid & 31;

    // logits scale folded with log2(e): phase 1 works directly in log2 domain
    const float s_l2 = 1.4426950408889634f / fmaxf(temperature[0], 1e-3f);

    // ---------- phase 1: row logits (log2 domain), block max, nse[8] in regs ----------
    const float4* wrow = reinterpret_cast<const float4*>(W_hh    + (size_t)o * H_);
    const float4* mrow = reinterpret_cast<const float4*>(hh_mask + (size_t)o * H_);
    float4 wa = wrow[tid], wb = wrow[tid + NT];
    float4 ma = mrow[tid], mb = mrow[tid + NT];
    float e[8];
    e[0] = wa.x*ma.x*s_l2; e[1] = wa.y*ma.y*s_l2; e[2] = wa.z*ma.z*s_l2; e[3] = wa.w*ma.w*s_l2;
    e[4] = wb.x*mb.x*s_l2; e[5] = wb.y*mb.y*s_l2; e[6] = wb.z*mb.z*s_l2; e[7] = wb.w*mb.w*s_l2;

    float m = e[0];
    #pragma unroll
    for (int j = 1; j < 8; j++) m = fmaxf(m, e[j]);
    #pragma unroll
    for (int s = 16; s; s >>= 1) m = fmaxf(m, __shfl_xor_sync(0xffffffffu, m, s));
    if (lid == 0) s_red[wid] = m;
    __syncthreads();
    m = s_red[0];
    #pragma unroll
    for (int j = 1; j < 8; j++) m = fmaxf(m, s_red[j]);

    // nse = -se * log2(e): sign + 1/ln2 folded so hot loop does w = nse * rcp(lg2 u)
    float nse[8];
    #pragma unroll
    for (int j = 0; j < 8; j++) nse[j] = -1.4426950408889634f * fex2(e[j] - m);

    // ---------- phase 3: stream gumbel (evict-first); rolling depth-1 prefetch ----------
    const size_t bstride4 = (size_t)H_ * H_ / 4;           // float4 stride between batches
    const float4* gu = reinterpret_cast<const float4*>(gumbel + (size_t)o * H_) + tid;
    const float4* pf = gu + bstride4;                      // prefetch: batch b+1
    const float4* hp = reinterpret_cast<const float4*>(h_prev) + tid;
    float2* sp = &s_part[0][tid];

    float4 ua = __ldcs(gu);
    float4 ub = __ldcs(gu + NT);

    #pragma unroll 4
    for (int b = 0; b < B_; b++) {
        const float4 na  = __ldcs(pf);                     // re-reads batch 15 on last iter
        const float4 nbv = __ldcs(pf + NT);
        const float4 ha  = __ldg(hp);
        const float4 hb  = __ldg(hp + NT);

        float n0 = 0.f, d0 = 0.f, n1 = 0.f, d1 = 0.f;     // dual accumulators: 2 chains
        float w;
        w = nse[0] * gwr(ua.x); n0 = fmaf(w, ha.x, n0); d0 += w;
        w = nse[1] * gwr(ua.y); n1 = fmaf(w, ha.y, n1); d1 += w;
        w = nse[2] * gwr(ua.z); n0 = fmaf(w, ha.z, n0); d0 += w;
        w = nse[3] * gwr(ua.w); n1 = fmaf(w, ha.w, n1); d1 += w;
        w = nse[4] * gwr(ub.x); n0 = fmaf(w, hb.x, n0); d0 += w;
        w = nse[5] * gwr(ub.y); n1 = fmaf(w, hb.y, n1); d1 += w;
        w = nse[6] * gwr(ub.z); n0 = fmaf(w, hb.z, n0); d0 += w;
        w = nse[7] * gwr(ub.w); n1 = fmaf(w, hb.w, n1); d1 += w;

        *sp = make_float2(n0 + n1, d0 + d1);               // contiguous 256B/warp

        ua = na; ub = nbv;
        pf += (b < B_ - 2) ? bstride4 : 0;                 // clamp: stay in-bounds
        hp += H_ / 4;
        sp += NT;
    }

    // ---------- phase 2: input contribution; warp w -> batches w and w+8 ----------
    // (after the gumbel stream so the DRAM-critical loop starts ASAP)
    {
        const float4* wr = reinterpret_cast<const float4*>(W_ih_w + (size_t)o * I_);
        const float4* x0 = reinterpret_cast<const float4*>(x_t + (size_t)wid * I_);
        const float4* x1 = reinterpret_cast<const float4*>(x_t + (size_t)(wid + 8) * I_);
        float a0 = 0.f, a1 = 0.f;
        #pragma unroll
        for (int k = lid; k < I_ / 4; k += 32) {
            float4 wv = wr[k];
            float4 v0 = x0[k];
            float4 v1 = x1[k];
            a0 = fmaf(wv.x, v0.x, a0); a0 = fmaf(wv.y, v0.y, a0);
            a0 = fmaf(wv.z, v0.z, a0); a0 = fmaf(wv.w, v0.w, a0);
            a1 = fmaf(wv.x, v1.x, a1); a1 = fmaf(wv.y, v1.y, a1);
            a1 = fmaf(wv.z, v1.z, a1); a1 = fmaf(wv.w, v1.w, a1);
        }
        #pragma unroll
        for (int s = 16; s; s >>= 1) {
            a0 += __shfl_xor_sync(0xffffffffu, a0, s);
            a1 += __shfl_xor_sync(0xffffffffu, a1, s);
        }
        if (lid == 0) {
            float bias = W_ih_b[o];
            s_ic[wid]     = a0 + bias;
            s_ic[wid + 8] = a1 + bias;
        }
    }
    __syncthreads();

    // ---------- phase 4: one-time reduction; warp w -> batches 2w, 2w+1 ----------
    #pragma unroll
    for (int k = 0; k < 2; k++) {
        const int b = 2 * wid + k;
        const float4* row = reinterpret_cast<const float4*>(&s_part[b][0]);   // 128 float4
        float4 p0 = row[lid], p1 = row[lid + 32], p2 = row[lid + 64], p3 = row[lid + 96];
        float ns = (p0.x + p1.x) + (p2.x + p3.x) + (p0.z + p1.z) + (p2.z + p3.z);
        float ds = (p0.y + p1.y) + (p2.y + p3.y) + (p0.w + p1.w) + (p2.w + p3.w);
        #pragma unroll
        for (int s = 16; s; s >>= 1) {
            ns += __shfl_xor_sync(0xffffffffu, ns, s);
            ds += __shfl_xor_sync(0xffffffffu, ds, s);
        }
        if (lid == 0) out[(size_t)b * H_ + o] = tanhf(s_ic[b] + ns / ds);
    }
}

extern "C" void kernel_launch(void* const* d_in, const int* in_sizes, int n_in,
                              void* d_out, int out_size) {
    const float* x_t         = (const float*)d_in[0];
    const float* h_prev      = (const float*)d_in[1];
    const float* W_ih_w      = (const float*)d_in[2];
    const float* W_ih_b      = (const float*)d_in[3];
    const float* W_hh        = (const float*)d_in[4];
    const float* hh_mask     = (const float*)d_in[5];
    const float* temperature = (const float*)d_in[6];
    const float* gumbel      = (const float*)d_in[7];
    float* out = (float*)d_out;

    reservoir_cell_kernel<<<H_, NT>>>(x_t, h_prev, W_ih_w, W_ih_b, W_hh, hh_mask,
                                      temperature, gumbel, out);
}